// round 2
// baseline (speedup 1.0000x reference)
#include <cuda_runtime.h>
#include <cstdint>

#define F_DIM   48
#define CHUNKS  12          // 48 floats = 12 float4 per edge

__constant__ float c_w[F_DIM];

// ---------------------------------------------------------------------------
// Kernel 1: zero the output (harness poisons d_out to 0xAA)
// ---------------------------------------------------------------------------
__global__ void zero_kernel(float4* __restrict__ out, int n4) {
    int i = blockIdx.x * blockDim.x + threadIdx.x;
    if (i < n4) out[i] = make_float4(0.f, 0.f, 0.f, 0.f);
}

// ---------------------------------------------------------------------------
// Kernel 2: fused gather * val * w -> vector red scatter-add.
// 12 consecutive threads own one edge PAIR; each thread handles chunk c of
// edges (2p, 2p+1). w comes from constant memory (constant port, not L1tex).
// ---------------------------------------------------------------------------
__global__ __launch_bounds__(256)
void gcn_scatter_kernel(const float* __restrict__ x,
                        const int*   __restrict__ rows,
                        const int*   __restrict__ cols,
                        const float* __restrict__ vals,
                        float*       __restrict__ out,
                        int nPairs, int nE) {
    int gid = blockIdx.x * blockDim.x + threadIdx.x;
    int p = gid / CHUNKS;
    int c = gid - p * CHUNKS;
    if (p >= nPairs) return;

    const int e0 = 2 * p;
    const int e1 = e0 + 1;
    const bool has1 = (e1 < nE);

    // Edge metadata (broadcast across the 12-lane group; coalesced across warp)
    const int   row0 = __ldg(rows + e0);
    const int   col0 = __ldg(cols + e0);
    const float v0   = __ldg(vals + e0);
    int   row1 = 0, col1 = col0;
    float v1   = 0.f;
    if (has1) {
        row1 = __ldg(rows + e1);
        col1 = __ldg(cols + e1);
        v1   = __ldg(vals + e1);
    }

    // Two independent gathers in flight (MLP)
    const float4 x0 = *reinterpret_cast<const float4*>(x + (size_t)col0 * F_DIM + c * 4);
    const float4 x1 = *reinterpret_cast<const float4*>(x + (size_t)col1 * F_DIM + c * 4);

    // Loop-invariant weights from the constant port
    const float w0 = c_w[c * 4 + 0];
    const float w1 = c_w[c * 4 + 1];
    const float w2 = c_w[c * 4 + 2];
    const float w3 = c_w[c * 4 + 3];

    float4 m0;
    m0.x = v0 * x0.x * w0;
    m0.y = v0 * x0.y * w1;
    m0.z = v0 * x0.z * w2;
    m0.w = v0 * x0.w * w3;

    float* dst0 = out + (size_t)row0 * F_DIM + c * 4;
    asm volatile("red.global.add.v4.f32 [%0], {%1, %2, %3, %4};"
                 :: "l"(dst0), "f"(m0.x), "f"(m0.y), "f"(m0.z), "f"(m0.w)
                 : "memory");

    if (has1) {
        float4 m1;
        m1.x = v1 * x1.x * w0;
        m1.y = v1 * x1.y * w1;
        m1.z = v1 * x1.z * w2;
        m1.w = v1 * x1.w * w3;
        float* dst1 = out + (size_t)row1 * F_DIM + c * 4;
        asm volatile("red.global.add.v4.f32 [%0], {%1, %2, %3, %4};"
                     :: "l"(dst1), "f"(m1.x), "f"(m1.y), "f"(m1.z), "f"(m1.w)
                     : "memory");
    }
}

// ---------------------------------------------------------------------------
// Launch
// Inputs: 0 x[1,100000,48] f32 | 1 w[1,48] f32 | 2 rows[1.6M] i32
//         3 cols[1.6M] i32     | 4 vals[1.6M] f32
// Output: f32 [100000, 48]
// ---------------------------------------------------------------------------
extern "C" void kernel_launch(void* const* d_in, const int* in_sizes, int n_in,
                              void* d_out, int out_size) {
    const float* x    = (const float*)d_in[0];
    const float* w    = (const float*)d_in[1];
    const int*   rows = (const int*)  d_in[2];
    const int*   cols = (const int*)  d_in[3];
    const float* vals = (const float*)d_in[4];
    float*       out  = (float*)d_out;

    const int nE   = in_sizes[2];
    const int nOut = out_size;

    // weights -> constant memory (device-to-device async copy; capturable)
    cudaMemcpyToSymbolAsync(c_w, w, F_DIM * sizeof(float), 0,
                            cudaMemcpyDeviceToDevice, 0);

    // zero out
    {
        int n4 = nOut / 4;
        int threads = 256;
        int blocks = (n4 + threads - 1) / threads;
        zero_kernel<<<blocks, threads>>>((float4*)out, n4);
    }

    // scatter
    {
        int nPairs = (nE + 1) / 2;
        long long total = (long long)nPairs * CHUNKS;
        int threads = 256;
        int blocks = (int)((total + threads - 1) / threads);
        gcn_scatter_kernel<<<blocks, threads>>>(x, rows, cols, vals, out, nPairs, nE);
    }
}

// round 3
// speedup vs baseline: 1.0624x; 1.0624x over previous
#include <cuda_runtime.h>
#include <cstdint>

#define F_DIM    48
#define CHUNKS   12          // 48 floats = 12 float4 per edge
#define N_NODES  100000

// Scratch: x pre-scaled by w (19.2 MB). __device__ global (no allocation).
__device__ float4 g_xw[N_NODES * CHUNKS];

// ---------------------------------------------------------------------------
// Kernel 1 (fused prologue): zero the output AND build xw = x * w.
// Both arrays are N_NODES*48 floats = N_NODES*12 float4.
// ---------------------------------------------------------------------------
__global__ __launch_bounds__(256)
void prologue_kernel(const float4* __restrict__ x4,
                     const float4* __restrict__ w4,   // 12 float4 (48 floats)
                     float4*       __restrict__ out4,
                     int n4) {
    int i = blockIdx.x * blockDim.x + threadIdx.x;
    if (i >= n4) return;

    out4[i] = make_float4(0.f, 0.f, 0.f, 0.f);

    int c = i % CHUNKS;                 // feature chunk of this element
    float4 xv = x4[i];
    float4 wv = __ldg(w4 + c);          // 192B, L1-resident
    xv.x *= wv.x; xv.y *= wv.y; xv.z *= wv.z; xv.w *= wv.w;
    g_xw[i] = xv;
}

// ---------------------------------------------------------------------------
// Kernel 2: gather xw[col] * val  ->  red.v4 scatter-add into out[row].
// 12 consecutive threads own one edge, one float4 chunk each.
// ---------------------------------------------------------------------------
__global__ __launch_bounds__(256)
void gcn_scatter_kernel(const int*   __restrict__ rows,
                        const int*   __restrict__ cols,
                        const float* __restrict__ vals,
                        float*       __restrict__ out,
                        int nE) {
    int gid = blockIdx.x * blockDim.x + threadIdx.x;
    int e = gid / CHUNKS;
    int c = gid - e * CHUNKS;
    if (e >= nE) return;

    const int   row = __ldg(rows + e);
    const int   col = __ldg(cols + e);
    const float v   = __ldg(vals + e);

    const float4 xv = g_xw[(size_t)col * CHUNKS + c];

    float4 m;
    m.x = v * xv.x;
    m.y = v * xv.y;
    m.z = v * xv.z;
    m.w = v * xv.w;

    float* dst = out + (size_t)row * F_DIM + c * 4;
    asm volatile("red.global.add.v4.f32 [%0], {%1, %2, %3, %4};"
                 :: "l"(dst), "f"(m.x), "f"(m.y), "f"(m.z), "f"(m.w)
                 : "memory");
}

// ---------------------------------------------------------------------------
// Launch
// Inputs: 0 x[1,100000,48] f32 | 1 w[1,48] f32 | 2 rows[1.6M] i32
//         3 cols[1.6M] i32     | 4 vals[1.6M] f32
// Output: f32 [100000, 48]
// ---------------------------------------------------------------------------
extern "C" void kernel_launch(void* const* d_in, const int* in_sizes, int n_in,
                              void* d_out, int out_size) {
    const float* x    = (const float*)d_in[0];
    const float* w    = (const float*)d_in[1];
    const int*   rows = (const int*)  d_in[2];
    const int*   cols = (const int*)  d_in[3];
    const float* vals = (const float*)d_in[4];
    float*       out  = (float*)d_out;

    const int nE   = in_sizes[2];          // 1,600,000
    const int nOut = out_size;             // 4,800,000 floats

    // prologue: zero out + xw = x*w
    {
        int n4 = nOut / 4;                 // 1.2M float4
        int threads = 256;
        int blocks = (n4 + threads - 1) / threads;
        prologue_kernel<<<blocks, threads>>>((const float4*)x, (const float4*)w,
                                             (float4*)out, n4);
    }

    // scatter
    {
        long long total = (long long)nE * CHUNKS;   // 19.2M threads
        int threads = 256;
        int blocks = (int)((total + threads - 1) / threads);
        gcn_scatter_kernel<<<blocks, threads>>>(rows, cols, vals, out, nE);
    }
}